// round 1
// baseline (speedup 1.0000x reference)
#include <cuda_runtime.h>
#include <cuda_bf16.h>
#include <math.h>

// Problem constants
#define B_  2
#define S_  2048
#define HID 2048
#define NH  16
#define NKV 4
#define DH  128
#define MROWS (B_ * S_)        // 4096
#define EPS 1e-6f

// ---------------- scratch (static device allocations are allowed) ----------------
__device__ float g_Q[(size_t)MROWS * NH * DH];   // 4096 x 2048
__device__ float g_K[(size_t)MROWS * NKV * DH];  // 4096 x 512
__device__ float g_V[(size_t)MROWS * NKV * DH];  // 4096 x 512
__device__ float g_O[(size_t)MROWS * NH * DH];   // 4096 x 2048

// ---------------- generic SGEMM: C[M,N] = A[M,K] @ B[K,N], all row-major ----------------
// BM=BN=128, BK=8, 256 threads, 8x8 per-thread micro-tile.
// Requires M%128==0, N%128==0, K%8==0 (true for all our shapes).
__global__ void __launch_bounds__(256) sgemm_kernel(
    const float* __restrict__ A, const float* __restrict__ Bm, float* __restrict__ C,
    int M, int N, int K)
{
    __shared__ float As[8][128];
    __shared__ float Bs[8][128];

    const int tid = threadIdx.x;
    const int bm = blockIdx.y * 128;
    const int bn = blockIdx.x * 128;
    const int tr = tid >> 4;        // 0..15
    const int tc = tid & 15;        // 0..15

    float acc[8][8];
#pragma unroll
    for (int i = 0; i < 8; i++)
#pragma unroll
        for (int j = 0; j < 8; j++) acc[i][j] = 0.f;

    const int ar  = tid >> 1;       // 0..127
    const int ac4 = tid & 1;        // 0..1
    const int br  = tid >> 5;       // 0..7
    const int bc4 = tid & 31;       // 0..31

    for (int k0 = 0; k0 < K; k0 += 8) {
        // Load A tile (128x8) transposed into As[k][m]
        float4 av = *(const float4*)(A + (size_t)(bm + ar) * K + k0 + ac4 * 4);
        As[ac4 * 4 + 0][ar] = av.x;
        As[ac4 * 4 + 1][ar] = av.y;
        As[ac4 * 4 + 2][ar] = av.z;
        As[ac4 * 4 + 3][ar] = av.w;
        // Load B tile (8x128)
        *(float4*)(&Bs[br][bc4 * 4]) =
            *(const float4*)(Bm + (size_t)(k0 + br) * N + bn + bc4 * 4);
        __syncthreads();

#pragma unroll
        for (int k = 0; k < 8; k++) {
            float ra[8], rb[8];
            float4 a0 = *(const float4*)(&As[k][tr * 8]);
            float4 a1 = *(const float4*)(&As[k][tr * 8 + 4]);
            float4 b0 = *(const float4*)(&Bs[k][tc * 8]);
            float4 b1 = *(const float4*)(&Bs[k][tc * 8 + 4]);
            ra[0]=a0.x; ra[1]=a0.y; ra[2]=a0.z; ra[3]=a0.w;
            ra[4]=a1.x; ra[5]=a1.y; ra[6]=a1.z; ra[7]=a1.w;
            rb[0]=b0.x; rb[1]=b0.y; rb[2]=b0.z; rb[3]=b0.w;
            rb[4]=b1.x; rb[5]=b1.y; rb[6]=b1.z; rb[7]=b1.w;
#pragma unroll
            for (int i = 0; i < 8; i++)
#pragma unroll
                for (int j = 0; j < 8; j++)
                    acc[i][j] += ra[i] * rb[j];
        }
        __syncthreads();
    }

#pragma unroll
    for (int i = 0; i < 8; i++) {
        size_t off = (size_t)(bm + tr * 8 + i) * N + bn + tc * 8;
        float4 c0 = make_float4(acc[i][0], acc[i][1], acc[i][2], acc[i][3]);
        float4 c1 = make_float4(acc[i][4], acc[i][5], acc[i][6], acc[i][7]);
        *(float4*)(C + off)     = c0;
        *(float4*)(C + off + 4) = c1;
    }
}

// ---------------- fused RMSNorm + RoPE (in place) ----------------
// One block of 128 threads per (row, head). buf layout: [row][head][DH].
__global__ void __launch_bounds__(128) rmsrope_kernel(
    float* __restrict__ buf, const float* __restrict__ w,
    const float* __restrict__ cosb, const float* __restrict__ sinb, int nheads)
{
    const int bh  = blockIdx.x;
    const int row = bh / nheads;
    const int h   = bh - row * nheads;
    const int s   = row & (S_ - 1);
    const int d   = threadIdx.x;

    float* p = buf + ((size_t)row * nheads + h) * DH;
    float v = p[d];

    float ss = v * v;
#pragma unroll
    for (int o = 16; o > 0; o >>= 1) ss += __shfl_xor_sync(0xffffffffu, ss, o);
    __shared__ float sh[4];
    if ((d & 31) == 0) sh[d >> 5] = ss;
    __syncthreads();
    float tot = sh[0] + sh[1] + sh[2] + sh[3];
    float inv = rsqrtf(tot * (1.0f / DH) + EPS);

    int pd = d ^ 64;               // rotate_half partner
    float pv  = p[pd];
    float nv  = w[d]  * v  * inv;
    float npv = w[pd] * pv * inv;
    float c  = cosb[(size_t)s * DH + d];
    float sn = sinb[(size_t)s * DH + d];
    float out = nv * c + ((d < 64) ? -npv : npv) * sn;
    __syncthreads();               // all reads complete before in-place write
    p[d] = out;
}

// ---------------- flash attention, fp32, causal ----------------
// Grid: (S/64, NH, B). 128 threads. BM=BN=64.
// smem: Qs[128][64] (d-major), Ks[64][129], Vs[64][128], Ps[64][64]
#define KS_STRIDE 129
#define FLASH_SMEM_FLOATS (128*64 + 64*KS_STRIDE + 64*128 + 64*64)

__global__ void __launch_bounds__(128) flash_kernel(
    const float* __restrict__ Qg, const float* __restrict__ Kg,
    const float* __restrict__ Vg, float* __restrict__ Og)
{
    extern __shared__ float smem[];
    float* Qs = smem;                      // [d][m]   128*64
    float* Ks = Qs + 128 * 64;             // [n][d]   64*129
    float* Vs = Ks + 64 * KS_STRIDE;       // [n][d]   64*128
    float* Ps = Vs + 64 * 128;             // [m][n]   64*64

    const int qt  = blockIdx.x;            // q tile
    const int h   = blockIdx.y;
    const int b   = blockIdx.z;
    const int kvh = h / (NH / NKV);
    const int tid = threadIdx.x;
    const int rg  = tid >> 4;              // 0..7  -> rows rg*8..+7
    const int cg  = tid & 15;              // 0..15 -> score cols cg*4..+3, out cols cg*8..+7
    const int r0  = rg * 8;
    const int c0  = cg * 4;

    const float scale = 0.08838834764831845f;   // 1/sqrt(128)

    // Load Q tile transposed (d-major), pre-scaled
    {
        const size_t qbase = ((size_t)(b * S_ + qt * 64)) * (NH * DH) + (size_t)h * DH;
#pragma unroll
        for (int i = tid; i < 64 * 32; i += 128) {
            int m = i >> 5, d4 = i & 31;
            float4 v = *(const float4*)(Qg + qbase + (size_t)m * (NH * DH) + d4 * 4);
            Qs[(d4 * 4 + 0) * 64 + m] = v.x * scale;
            Qs[(d4 * 4 + 1) * 64 + m] = v.y * scale;
            Qs[(d4 * 4 + 2) * 64 + m] = v.z * scale;
            Qs[(d4 * 4 + 3) * 64 + m] = v.w * scale;
        }
    }

    float acc[8][8];
#pragma unroll
    for (int i = 0; i < 8; i++)
#pragma unroll
        for (int j = 0; j < 8; j++) acc[i][j] = 0.f;
    float mrow[8], lrow[8];
#pragma unroll
    for (int i = 0; i < 8; i++) { mrow[i] = -1e30f; lrow[i] = 0.f; }

    for (int kt = 0; kt <= qt; kt++) {
        // Load K (padded rows) and V tiles
        const size_t kbase = ((size_t)(b * S_ + kt * 64)) * (NKV * DH) + (size_t)kvh * DH;
#pragma unroll
        for (int i = tid; i < 64 * 32; i += 128) {
            int n = i >> 5, d4 = i & 31;
            float4 kv = *(const float4*)(Kg + kbase + (size_t)n * (NKV * DH) + d4 * 4);
            Ks[n * KS_STRIDE + d4 * 4 + 0] = kv.x;
            Ks[n * KS_STRIDE + d4 * 4 + 1] = kv.y;
            Ks[n * KS_STRIDE + d4 * 4 + 2] = kv.z;
            Ks[n * KS_STRIDE + d4 * 4 + 3] = kv.w;
            float4 vv = *(const float4*)(Vg + kbase + (size_t)n * (NKV * DH) + d4 * 4);
            *(float4*)(Vs + n * 128 + d4 * 4) = vv;
        }
        __syncthreads();

        // Scores: s[8 rows][4 cols]
        float s[8][4];
#pragma unroll
        for (int i = 0; i < 8; i++)
#pragma unroll
            for (int j = 0; j < 4; j++) s[i][j] = 0.f;

#pragma unroll 4
        for (int d = 0; d < 128; d++) {
            float4 qa = *(const float4*)(Qs + d * 64 + r0);
            float4 qb = *(const float4*)(Qs + d * 64 + r0 + 4);
            float qv[8] = {qa.x, qa.y, qa.z, qa.w, qb.x, qb.y, qb.z, qb.w};
            float kv[4];
#pragma unroll
            for (int j = 0; j < 4; j++) kv[j] = Ks[(c0 + j) * KS_STRIDE + d];
#pragma unroll
            for (int i = 0; i < 8; i++)
#pragma unroll
                for (int j = 0; j < 4; j++)
                    s[i][j] += qv[i] * kv[j];
        }

        // Causal mask on the diagonal tile
        if (kt == qt) {
#pragma unroll
            for (int i = 0; i < 8; i++)
#pragma unroll
                for (int j = 0; j < 4; j++)
                    if (c0 + j > r0 + i) s[i][j] = -1e30f;
        }

        // Online softmax update
#pragma unroll
        for (int i = 0; i < 8; i++) {
            float mx = s[i][0];
            mx = fmaxf(mx, s[i][1]); mx = fmaxf(mx, s[i][2]); mx = fmaxf(mx, s[i][3]);
#pragma unroll
            for (int o = 8; o > 0; o >>= 1)
                mx = fmaxf(mx, __shfl_xor_sync(0xffffffffu, mx, o));
            float mnew = fmaxf(mrow[i], mx);
            float f = __expf(mrow[i] - mnew);
            mrow[i] = mnew;
            float ls = 0.f;
#pragma unroll
            for (int j = 0; j < 4; j++) {
                float pj = __expf(s[i][j] - mnew);
                s[i][j] = pj;
                ls += pj;
            }
#pragma unroll
            for (int o = 8; o > 0; o >>= 1)
                ls += __shfl_xor_sync(0xffffffffu, ls, o);
            lrow[i] = lrow[i] * f + ls;
#pragma unroll
            for (int j = 0; j < 8; j++) acc[i][j] *= f;
            // stash probs
#pragma unroll
            for (int j = 0; j < 4; j++)
                Ps[(r0 + i) * 64 + c0 + j] = s[i][j];
        }
        __syncthreads();

        // acc += P @ V  (out cols cg*8..+7)
#pragma unroll 2
        for (int n = 0; n < 64; n++) {
            float4 va = *(const float4*)(Vs + n * 128 + cg * 8);
            float4 vb = *(const float4*)(Vs + n * 128 + cg * 8 + 4);
            float vv[8] = {va.x, va.y, va.z, va.w, vb.x, vb.y, vb.z, vb.w};
#pragma unroll
            for (int i = 0; i < 8; i++) {
                float p = Ps[(r0 + i) * 64 + n];
#pragma unroll
                for (int j = 0; j < 8; j++)
                    acc[i][j] += p * vv[j];
            }
        }
        __syncthreads();   // before next tile overwrites Ks/Vs/Ps
    }

    // Epilogue: divide by l, write to O [row][h*DH + col]
    const size_t obase = ((size_t)(b * S_ + qt * 64)) * (NH * DH) + (size_t)h * DH;
#pragma unroll
    for (int i = 0; i < 8; i++) {
        float invl = 1.0f / lrow[i];
        float4 o0 = make_float4(acc[i][0] * invl, acc[i][1] * invl,
                                acc[i][2] * invl, acc[i][3] * invl);
        float4 o1 = make_float4(acc[i][4] * invl, acc[i][5] * invl,
                                acc[i][6] * invl, acc[i][7] * invl);
        size_t off = obase + (size_t)(r0 + i) * (NH * DH) + cg * 8;
        *(float4*)(Og + off)     = o0;
        *(float4*)(Og + off + 4) = o1;
    }
}

// ---------------- launch ----------------
extern "C" void kernel_launch(void* const* d_in, const int* in_sizes, int n_in,
                              void* d_out, int out_size)
{
    const float* X    = (const float*)d_in[0];
    // d_in[1] = attention_mask: exact causal mask, applied analytically — unused
    const float* cosp = (const float*)d_in[2];
    const float* sinp = (const float*)d_in[3];
    const float* Wq   = (const float*)d_in[4];
    const float* Wk   = (const float*)d_in[5];
    const float* Wv   = (const float*)d_in[6];
    const float* Wo   = (const float*)d_in[7];
    const float* qnw  = (const float*)d_in[8];
    const float* knw  = (const float*)d_in[9];
    float* out = (float*)d_out;

    float *Q, *K, *V, *O;
    cudaGetSymbolAddress((void**)&Q, g_Q);
    cudaGetSymbolAddress((void**)&K, g_K);
    cudaGetSymbolAddress((void**)&V, g_V);
    cudaGetSymbolAddress((void**)&O, g_O);

    // QKV projections
    sgemm_kernel<<<dim3(NH * DH / 128, MROWS / 128), 256>>>(X, Wq, Q, MROWS, NH * DH, HID);
    sgemm_kernel<<<dim3(NKV * DH / 128, MROWS / 128), 256>>>(X, Wk, K, MROWS, NKV * DH, HID);
    sgemm_kernel<<<dim3(NKV * DH / 128, MROWS / 128), 256>>>(X, Wv, V, MROWS, NKV * DH, HID);

    // RMSNorm + RoPE
    rmsrope_kernel<<<MROWS * NH, 128>>>(Q, qnw, cosp, sinp, NH);
    rmsrope_kernel<<<MROWS * NKV, 128>>>(K, knw, cosp, sinp, NKV);

    // Flash attention
    static const size_t flash_smem = (size_t)FLASH_SMEM_FLOATS * sizeof(float);
    cudaFuncSetAttribute(flash_kernel, cudaFuncAttributeMaxDynamicSharedMemorySize,
                         (int)flash_smem);
    flash_kernel<<<dim3(S_ / 64, NH, B_), 128, flash_smem>>>(Q, K, V, O);

    // Output projection
    sgemm_kernel<<<dim3(HID / 128, MROWS / 128), 256>>>(O, Wo, out, MROWS, HID, HID);
}